// round 1
// baseline (speedup 1.0000x reference)
#include <cuda_runtime.h>
#include <math.h>

// ---------------- problem constants ----------------
#define S_ROWS 2047          // N_PART - 1
#define DIM    256
#define HID    512
#define NB     16            // N_BINS
#define NFREQ  8
#define NBLK   4
#define NHEAD  8
#define DH     32
#define EMB_IN 35            // 2*8*2 + 3
#define AFF_OUT 49           // 3*16 + 1
#define POS_ELEMS (2048*3)

// ---------------- scratch (static device memory; no allocs allowed) -------
__device__ float g_cond[S_ROWS * EMB_IN];
__device__ float g_a[S_ROWS * HID];
__device__ float g_b[S_ROWS * HID];
__device__ float g_h[S_ROWS * DIM];
__device__ float g_t[S_ROWS * DIM];     // attention output
__device__ float g_q[S_ROWS * DIM];
__device__ float g_k[S_ROWS * DIM];
__device__ float g_v[S_ROWS * DIM];
__device__ float g_params[S_ROWS * AFF_OUT];
__device__ float g_ld[S_ROWS];

// ---------------- circular features + conditioning vector -----------------
__global__ void embed_kernel(const float* __restrict__ pos,
                             const float* __restrict__ scale,
                             const float* __restrict__ press,
                             const float* __restrict__ temp,
                             float* __restrict__ cond) {
    int s = blockIdx.x * blockDim.x + threadIdx.x;
    if (s >= S_ROWS) return;
    const float TWO_PI = 6.28318530717958647692f;
    float xs[2];
    xs[0] = pos[(s + 1) * 3 + 0];
    xs[1] = pos[(s + 1) * 3 + 1];
    float* c = cond + s * EMB_IN;
    #pragma unroll
    for (int cc = 0; cc < 2; cc++) {
        float x = xs[cc];
        #pragma unroll
        for (int f = 1; f <= NFREQ; f++) {
            float sn, cs;
            sincosf(TWO_PI * (float)f * x, &sn, &cs);
            c[cc * 16 + (f - 1)]     = cs;
            c[cc * 16 + 8 + (f - 1)] = sn;
        }
    }
    c[32] = *scale;
    c[33] = *temp;
    c[34] = *press;
}

// ---------------- tiled fp32 GEMM: C = A(SxK) @ W(NxK)^T (+bias)(+res)(relu)
template <bool RELU>
__global__ void gemm_kernel(const float* __restrict__ A,
                            const float* __restrict__ W,
                            const float* __restrict__ bias,
                            const float* __restrict__ res,
                            float* __restrict__ C,
                            int S, int N, int K) {
    __shared__ float As[16][64];
    __shared__ float Bs[16][64];
    int tx = threadIdx.x & 15;
    int ty = threadIdx.x >> 4;
    int m0 = blockIdx.y * 64;
    int n0 = blockIdx.x * 64;

    float c[4][4];
    #pragma unroll
    for (int i = 0; i < 4; i++)
        #pragma unroll
        for (int j = 0; j < 4; j++) c[i][j] = 0.f;

    for (int k0 = 0; k0 < K; k0 += 16) {
        for (int idx = threadIdx.x; idx < 64 * 16; idx += 256) {
            int kk = idx & 15, mm = idx >> 4;
            int m = m0 + mm, k = k0 + kk;
            As[kk][mm] = (m < S && k < K) ? A[m * K + k] : 0.f;
        }
        for (int idx = threadIdx.x; idx < 64 * 16; idx += 256) {
            int kk = idx & 15, nn = idx >> 4;
            int n = n0 + nn, k = k0 + kk;
            Bs[kk][nn] = (n < N && k < K) ? W[n * K + k] : 0.f;
        }
        __syncthreads();
        #pragma unroll
        for (int k = 0; k < 16; k++) {
            float4 a4 = *(const float4*)&As[k][ty * 4];
            float4 b4 = *(const float4*)&Bs[k][tx * 4];
            float av[4] = {a4.x, a4.y, a4.z, a4.w};
            float bv[4] = {b4.x, b4.y, b4.z, b4.w};
            #pragma unroll
            for (int i = 0; i < 4; i++)
                #pragma unroll
                for (int j = 0; j < 4; j++) c[i][j] += av[i] * bv[j];
        }
        __syncthreads();
    }

    #pragma unroll
    for (int i = 0; i < 4; i++) {
        int m = m0 + ty * 4 + i;
        if (m >= S) continue;
        #pragma unroll
        for (int j = 0; j < 4; j++) {
            int n = n0 + tx * 4 + j;
            if (n >= N) continue;
            float v = c[i][j];
            if (bias) v += bias[n];
            if (res)  v += res[m * N + n];
            if (RELU) v = fmaxf(v, 0.f);
            C[m * N + n] = v;
        }
    }
}

static void gemm(const float* A, const float* W, const float* bias,
                 const float* res, float* C, int S, int N, int K, bool relu) {
    dim3 grid((N + 63) / 64, (S + 63) / 64);
    if (relu) gemm_kernel<true ><<<grid, 256>>>(A, W, bias, res, C, S, N, K);
    else      gemm_kernel<false><<<grid, 256>>>(A, W, bias, res, C, S, N, K);
}

// ---------------- flash attention (fp32, online softmax) ------------------
// grid: (ceil(S/64), NHEAD), 128 threads. thread -> (row = tid>>1, half = tid&1)
__global__ void flash_kernel(const float* __restrict__ q,
                             const float* __restrict__ k,
                             const float* __restrict__ v,
                             float* __restrict__ o) {
    const int S = S_ROWS, D = DIM;
    int head = blockIdx.y;
    int s0 = blockIdx.x * 64;
    int tid = threadIdx.x;
    int row = tid >> 1;
    int half = tid & 1;

    __shared__ float ks[64][33];
    __shared__ float vs[64][33];
    __shared__ float ps[64][65];

    // q row for this thread in registers
    float qreg[32];
    int srow = s0 + row;
    #pragma unroll
    for (int d = 0; d < 32; d++)
        qreg[d] = (srow < S) ? q[srow * D + head * 32 + d] : 0.f;

    float acc[16];
    #pragma unroll
    for (int i = 0; i < 16; i++) acc[i] = 0.f;
    float m = -INFINITY, l = 0.f;
    const float scl = 0.17677669529663688f; // 1/sqrt(32)

    for (int t0 = 0; t0 < S; t0 += 64) {
        for (int idx = tid; idx < 64 * 32; idx += 128) {
            int r = idx >> 5, d = idx & 31;
            int t = t0 + r;
            ks[r][d] = (t < S) ? k[t * D + head * 32 + d] : 0.f;
            vs[r][d] = (t < S) ? v[t * D + head * 32 + d] : 0.f;
        }
        __syncthreads();

        float p[32];
        float mloc = -INFINITY;
        #pragma unroll
        for (int j = 0; j < 32; j++) {
            int t = half * 32 + j;
            float sc;
            if (t0 + t < S) {
                sc = 0.f;
                #pragma unroll
                for (int d = 0; d < 32; d++) sc += qreg[d] * ks[t][d];
                sc *= scl;
            } else {
                sc = -INFINITY;
            }
            p[j] = sc;
            mloc = fmaxf(mloc, sc);
        }
        mloc = fmaxf(mloc, __shfl_xor_sync(0xffffffffu, mloc, 1));
        float mnew = fmaxf(m, mloc);
        float corr = expf(m - mnew);
        float lloc = 0.f;
        #pragma unroll
        for (int j = 0; j < 32; j++) {
            float e = expf(p[j] - mnew);   // -inf -> 0
            lloc += e;
            ps[row][half * 32 + j] = e;
        }
        lloc += __shfl_xor_sync(0xffffffffu, lloc, 1);
        l = l * corr + lloc;
        m = mnew;
        #pragma unroll
        for (int i = 0; i < 16; i++) acc[i] *= corr;
        __syncwarp();
        for (int t = 0; t < 64; t++) {
            float pv = ps[row][t];
            #pragma unroll
            for (int i = 0; i < 16; i++) acc[i] += pv * vs[t][half * 16 + i];
        }
        __syncthreads();
    }

    if (srow < S) {
        float inv = 1.f / l;
        #pragma unroll
        for (int i = 0; i < 16; i++)
            o[srow * D + head * 32 + half * 16 + i] = acc[i] * inv;
    }
}

// ---------------- RQS spline ------------------------------------------------
__device__ __forceinline__ float softplusf(float x) {
    return (x > 20.f) ? x : log1pf(expf(x));
}

__global__ void spline_kernel(const float* __restrict__ pos,
                              const float* __restrict__ params,
                              float* __restrict__ out,
                              float* __restrict__ ld) {
    int s = blockIdx.x * blockDim.x + threadIdx.x;
    if (s >= S_ROWS) return;
    const float* p = params + s * AFF_OUT;
    const float MINB = 1e-4f;
    const float MINS = 1e-4f;

    float x = pos[(s + 1) * 3 + 2];
    bool inside = (x >= 0.f) && (x <= 1.f);
    float xc = fminf(fmaxf(x, 0.f), 1.f);

    // softmax widths / heights
    float ew[NB], eh[NB];
    float mw = -INFINITY, mh = -INFINITY;
    #pragma unroll
    for (int i = 0; i < NB; i++) { mw = fmaxf(mw, p[i]); mh = fmaxf(mh, p[NB + i]); }
    float sw = 0.f, sh = 0.f;
    #pragma unroll
    for (int i = 0; i < NB; i++) {
        ew[i] = expf(p[i] - mw);        sw += ew[i];
        eh[i] = expf(p[NB + i] - mh);   sh += eh[i];
    }
    float fac = 1.f - NB * MINB;
    float isw = fac / sw, ish = fac / sh;

    // slopes (periodic last = first)
    float off = logf(expm1f(1.f - MINS));
    float d[NB + 1];
    #pragma unroll
    for (int i = 0; i < NB; i++) d[i] = softplusf(p[2 * NB + i] + off) + MINS;
    d[NB] = d[0];

    // cumulative knots
    float xp[NB + 1], yp[NB + 1];
    xp[0] = 0.f; yp[0] = 0.f;
    #pragma unroll
    for (int i = 0; i < NB; i++) {
        xp[i + 1] = xp[i] + (ew[i] * isw + MINB);
        yp[i + 1] = yp[i] + (eh[i] * ish + MINB);
    }

    int cnt = 0;
    #pragma unroll
    for (int i = 0; i < NB + 1; i++) cnt += (xc >= xp[i]) ? 1 : 0;
    int kb = cnt - 1;
    if (kb < 0) kb = 0;
    if (kb > NB - 1) kb = NB - 1;

    float xk = xp[kb], xk1 = xp[kb + 1];
    float yk = yp[kb], yk1 = yp[kb + 1];
    float dk = d[kb],  dk1 = d[kb + 1];
    float w = xk1 - xk;
    float h = yk1 - yk;
    float sl = h / w;
    float z = (xc - xk) / w;
    float z1 = 1.f - z;
    float den = sl + (dk1 + dk - 2.f * sl) * z * z1;
    float y = yk + h * (sl * z * z + dk * z * z1) / den;
    float logdet = 2.f * logf(sl)
                 + logf(dk1 * z * z + 2.f * sl * z * z1 + dk * z1 * z1)
                 - 2.f * logf(den);

    out[(s + 1) * 3 + 2] = inside ? y : x;
    ld[s] = inside ? logdet : 0.f;
}

// ---------------- output copy + deterministic logdet reduction -------------
__global__ void copy_pos_kernel(const float* __restrict__ pos,
                                float* __restrict__ out, int n) {
    int i = blockIdx.x * blockDim.x + threadIdx.x;
    if (i < n) out[i] = pos[i];
}

__global__ void reduce_kernel(const float* __restrict__ ld,
                              float* __restrict__ out, int out_size) {
    __shared__ float sh[256];
    float s = 0.f;
    for (int i = threadIdx.x; i < S_ROWS; i += 256) s += ld[i];
    sh[threadIdx.x] = s;
    __syncthreads();
    for (int st = 128; st > 0; st >>= 1) {
        if (threadIdx.x < st) sh[threadIdx.x] += sh[threadIdx.x + st];
        __syncthreads();
    }
    if (threadIdx.x == 0 && out_size > POS_ELEMS) out[POS_ELEMS] = sh[0];
}

// ---------------- host orchestration ---------------------------------------
template <typename T>
static float* sym_addr(T& sym) {
    void* p = nullptr;
    cudaGetSymbolAddress(&p, sym);
    return (float*)p;
}

extern "C" void kernel_launch(void* const* d_in, const int* in_sizes, int n_in,
                              void* d_out, int out_size) {
    const float* pos   = (const float*)d_in[0];
    const float* scale = (const float*)d_in[1];
    const float* press = (const float*)d_in[2];
    const float* temp  = (const float*)d_in[3];
    const float* e_w0 = (const float*)d_in[4];
    const float* e_b0 = (const float*)d_in[5];
    const float* e_w1 = (const float*)d_in[6];
    const float* e_b1 = (const float*)d_in[7];
    const float* e_w2 = (const float*)d_in[8];
    const float* e_b2 = (const float*)d_in[9];
    const float* Wq   = (const float*)d_in[10];
    const float* Wk   = (const float*)d_in[11];
    const float* bk   = (const float*)d_in[12];
    const float* Wv   = (const float*)d_in[13];
    const float* Wo   = (const float*)d_in[14];
    const float* bo   = (const float*)d_in[15];
    const float* mw0  = (const float*)d_in[16];
    const float* mb0  = (const float*)d_in[17];
    const float* mw1  = (const float*)d_in[18];
    const float* mb1  = (const float*)d_in[19];
    const float* mw2  = (const float*)d_in[20];
    const float* mb2  = (const float*)d_in[21];
    const float* a_w0 = (const float*)d_in[22];
    const float* a_b0 = (const float*)d_in[23];
    const float* a_w1 = (const float*)d_in[24];
    const float* a_b1 = (const float*)d_in[25];
    const float* a_w2 = (const float*)d_in[26];
    const float* a_b2 = (const float*)d_in[27];

    float* cond   = sym_addr(g_cond);
    float* bufA   = sym_addr(g_a);
    float* bufB   = sym_addr(g_b);
    float* h      = sym_addr(g_h);
    float* t      = sym_addr(g_t);
    float* q      = sym_addr(g_q);
    float* k      = sym_addr(g_k);
    float* v      = sym_addr(g_v);
    float* params = sym_addr(g_params);
    float* ld     = sym_addr(g_ld);
    float* out    = (float*)d_out;

    // features + conditioning
    embed_kernel<<<(S_ROWS + 255) / 256, 256>>>(pos, scale, press, temp, cond);

    // embedding MLP: 35 -> 512 -> 512 -> 256
    gemm(cond, e_w0, e_b0, nullptr, bufA, S_ROWS, HID, EMB_IN, true);
    gemm(bufA, e_w1, e_b1, nullptr, bufB, S_ROWS, HID, HID, true);
    gemm(bufB, e_w2, e_b2, nullptr, h,    S_ROWS, DIM, HID, false);

    // transformer blocks
    for (int i = 0; i < NBLK; i++) {
        const float* Wqi = Wq + (size_t)i * DIM * DIM;
        const float* Wki = Wk + (size_t)i * DIM * DIM;
        const float* bki = bk + (size_t)i * DIM;
        const float* Wvi = Wv + (size_t)i * DIM * DIM;
        const float* Woi = Wo + (size_t)i * DIM * DIM;
        const float* boi = bo + (size_t)i * DIM;
        const float* mw0i = mw0 + (size_t)i * HID * DIM;
        const float* mb0i = mb0 + (size_t)i * HID;
        const float* mw1i = mw1 + (size_t)i * HID * HID;
        const float* mb1i = mb1 + (size_t)i * HID;
        const float* mw2i = mw2 + (size_t)i * DIM * HID;
        const float* mb2i = mb2 + (size_t)i * DIM;

        gemm(h, Wqi, nullptr, nullptr, q, S_ROWS, DIM, DIM, false);
        gemm(h, Wki, bki,     nullptr, k, S_ROWS, DIM, DIM, false);
        gemm(h, Wvi, nullptr, nullptr, v, S_ROWS, DIM, DIM, false);

        dim3 fgrid((S_ROWS + 63) / 64, NHEAD);
        flash_kernel<<<fgrid, 128>>>(q, k, v, t);

        // h = h + o @ Wo^T + bo
        gemm(t, Woi, boi, h, h, S_ROWS, DIM, DIM, false);

        // h = h + MLP(h)
        gemm(h,    mw0i, mb0i, nullptr, bufA, S_ROWS, HID, DIM, true);
        gemm(bufA, mw1i, mb1i, nullptr, bufB, S_ROWS, HID, HID, true);
        gemm(bufB, mw2i, mb2i, h,       h,    S_ROWS, DIM, HID, false);
    }

    // affine head: 256 -> 512 -> 512 -> 49
    gemm(h,    a_w0, a_b0, nullptr, bufA,   S_ROWS, HID,     DIM, true);
    gemm(bufA, a_w1, a_b1, nullptr, bufB,   S_ROWS, HID,     HID, true);
    gemm(bufB, a_w2, a_b2, nullptr, params, S_ROWS, AFF_OUT, HID, false);

    // outputs
    int ncopy = out_size < POS_ELEMS ? out_size : POS_ELEMS;
    copy_pos_kernel<<<(ncopy + 255) / 256, 256>>>(pos, out, ncopy);
    spline_kernel<<<(S_ROWS + 255) / 256, 256>>>(pos, params, out, ld);
    reduce_kernel<<<1, 256>>>(ld, out, out_size);
}

// round 3
// speedup vs baseline: 1.6040x; 1.6040x over previous
#include <cuda_runtime.h>
#include <cstdint>
#include <math.h>

// ---------------- problem constants ----------------
#define S_ROWS 2047          // N_PART - 1
#define DIM    256
#define HID    512
#define NB     16            // N_BINS
#define NFREQ  8
#define NBLK   4
#define NHEAD  8
#define EMB_IN 35            // 2*8*2 + 3
#define AFF_OUT 49           // 3*16 + 1
#define POS_ELEMS (2048*3)

// ---------------- scratch (static device memory; no allocs allowed) -------
__device__ float g_cond[S_ROWS * EMB_IN];
__device__ float g_a[S_ROWS * HID];
__device__ float g_b[S_ROWS * HID];
__device__ float g_h[S_ROWS * DIM];
__device__ float g_t[S_ROWS * DIM];
__device__ float g_q[S_ROWS * DIM];
__device__ float g_k[S_ROWS * DIM];
__device__ float g_v[S_ROWS * DIM];
__device__ float g_params[S_ROWS * AFF_OUT];
__device__ float g_ld[S_ROWS];

// ---------------- helpers ---------------------------------------------------
__device__ __forceinline__ uint32_t f2tf32(float f) {
    uint32_t u;
    asm("cvt.rna.tf32.f32 %0, %1;" : "=r"(u) : "f"(f));
    return u;
}

__device__ __forceinline__ void mma_tf32(float c[4], const uint32_t a[4],
                                         const uint32_t b[2]) {
    asm volatile(
        "mma.sync.aligned.m16n8k8.row.col.f32.tf32.tf32.f32 "
        "{%0,%1,%2,%3}, {%4,%5,%6,%7}, {%8,%9}, {%0,%1,%2,%3};"
        : "+f"(c[0]), "+f"(c[1]), "+f"(c[2]), "+f"(c[3])
        : "r"(a[0]), "r"(a[1]), "r"(a[2]), "r"(a[3]), "r"(b[0]), "r"(b[1]));
}

// ---------------- circular features + conditioning vector -----------------
__global__ void embed_kernel(const float* __restrict__ pos,
                             const float* __restrict__ scale,
                             const float* __restrict__ press,
                             const float* __restrict__ temp,
                             float* __restrict__ cond) {
    int s = blockIdx.x * blockDim.x + threadIdx.x;
    if (s >= S_ROWS) return;
    const float TWO_PI = 6.28318530717958647692f;
    float xs[2];
    xs[0] = pos[(s + 1) * 3 + 0];
    xs[1] = pos[(s + 1) * 3 + 1];
    float* c = cond + s * EMB_IN;
    #pragma unroll
    for (int cc = 0; cc < 2; cc++) {
        float x = xs[cc];
        #pragma unroll
        for (int f = 1; f <= NFREQ; f++) {
            float sn, cs;
            sincosf(TWO_PI * (float)f * x, &sn, &cs);
            c[cc * 16 + (f - 1)]     = cs;
            c[cc * 16 + 8 + (f - 1)] = sn;
        }
    }
    c[32] = *scale;
    c[33] = *temp;
    c[34] = *press;
}

// ---------------- 3xTF32 tensor-core GEMM ----------------------------------
// C[SxN] = A[SxK] @ W[NxK]^T (+bias)(+res)(relu), near-fp32 accuracy via
// error-compensated tf32: C = Ahi*Bhi + Ahi*Blo + Alo*Bhi.
// Block tile 64x64, 256 threads = 8 warps in 2(m) x 4(n); warp tile 32x16.
template <bool RELU>
__global__ __launch_bounds__(256)
void gemm_tc_kernel(const float* __restrict__ A,
                    const float* __restrict__ W,
                    const float* __restrict__ bias,
                    const float* __restrict__ res,
                    float* __restrict__ C,
                    int S, int N, int K) {
    __shared__ uint32_t AsH[64][36];
    __shared__ uint32_t AsL[64][36];
    __shared__ uint32_t BsH[64][36];
    __shared__ uint32_t BsL[64][36];

    const int tid  = threadIdx.x;
    const int lane = tid & 31;
    const int wid  = tid >> 5;
    const int warp_m = wid >> 2;        // 0..1 (32 rows each)
    const int warp_n = wid & 3;         // 0..3 (16 cols each)
    const int g   = lane >> 2;          // groupID 0..7
    const int tig = lane & 3;           // thread-in-group 0..3

    const int m0 = blockIdx.y * 64;
    const int n0 = blockIdx.x * 64;

    // global-load mapping: 2 float4 per thread per operand per stage
    int aRow[2], aCol[2];
    #pragma unroll
    for (int i = 0; i < 2; i++) {
        int f4 = i * 256 + tid;         // 0..511
        aRow[i] = f4 >> 3;              // 0..63
        aCol[i] = (f4 & 7) * 4;         // 0,4,...,28
    }

    float avp[2][4], bvp[2][4];
    const int nStages = (K + 31) / 32;

    // prologue: load stage 0 into registers
    {
        #pragma unroll
        for (int i = 0; i < 2; i++) {
            int m = m0 + aRow[i];
            int k = aCol[i];
            #pragma unroll
            for (int j = 0; j < 4; j++)
                avp[i][j] = (m < S && (k + j) < K) ? A[(size_t)m * K + k + j] : 0.f;
            int n = n0 + aRow[i];
            #pragma unroll
            for (int j = 0; j < 4; j++)
                bvp[i][j] = (n < N && (k + j) < K) ? W[(size_t)n * K + k + j] : 0.f;
        }
    }

    float c[2][2][4];
    #pragma unroll
    for (int mt = 0; mt < 2; mt++)
        #pragma unroll
        for (int nt = 0; nt < 2; nt++)
            #pragma unroll
            for (int i = 0; i < 4; i++) c[mt][nt][i] = 0.f;

    for (int s = 0; s < nStages; s++) {
        // commit prefetched registers to smem (hi/lo tf32 split)
        #pragma unroll
        for (int i = 0; i < 2; i++) {
            #pragma unroll
            for (int j = 0; j < 4; j++) {
                float a = avp[i][j];
                uint32_t ah = f2tf32(a);
                AsH[aRow[i]][aCol[i] + j] = ah;
                AsL[aRow[i]][aCol[i] + j] = f2tf32(a - __uint_as_float(ah));
                float b = bvp[i][j];
                uint32_t bh = f2tf32(b);
                BsH[aRow[i]][aCol[i] + j] = bh;
                BsL[aRow[i]][aCol[i] + j] = f2tf32(b - __uint_as_float(bh));
            }
        }
        __syncthreads();

        // prefetch next stage
        if (s + 1 < nStages) {
            const int k0 = (s + 1) * 32;
            #pragma unroll
            for (int i = 0; i < 2; i++) {
                int m = m0 + aRow[i];
                int k = k0 + aCol[i];
                #pragma unroll
                for (int j = 0; j < 4; j++)
                    avp[i][j] = (m < S && (k + j) < K) ? A[(size_t)m * K + k + j] : 0.f;
                int n = n0 + aRow[i];
                #pragma unroll
                for (int j = 0; j < 4; j++)
                    bvp[i][j] = (n < N && (k + j) < K) ? W[(size_t)n * K + k + j] : 0.f;
            }
        }

        // mma over the 32-wide k slab
        #pragma unroll
        for (int k8 = 0; k8 < 4; k8++) {
            const int kk = k8 * 8;
            uint32_t aH[2][4], aL[2][4];
            #pragma unroll
            for (int mt = 0; mt < 2; mt++) {
                int r = warp_m * 32 + mt * 16 + g;
                aH[mt][0] = AsH[r    ][kk + tig];
                aH[mt][1] = AsH[r + 8][kk + tig];
                aH[mt][2] = AsH[r    ][kk + tig + 4];
                aH[mt][3] = AsH[r + 8][kk + tig + 4];
                aL[mt][0] = AsL[r    ][kk + tig];
                aL[mt][1] = AsL[r + 8][kk + tig];
                aL[mt][2] = AsL[r    ][kk + tig + 4];
                aL[mt][3] = AsL[r + 8][kk + tig + 4];
            }
            uint32_t bH[2][2], bL[2][2];
            #pragma unroll
            for (int nt = 0; nt < 2; nt++) {
                int cidx = warp_n * 16 + nt * 8 + g;
                bH[nt][0] = BsH[cidx][kk + tig];
                bH[nt][1] = BsH[cidx][kk + tig + 4];
                bL[nt][0] = BsL[cidx][kk + tig];
                bL[nt][1] = BsL[cidx][kk + tig + 4];
            }
            #pragma unroll
            for (int mt = 0; mt < 2; mt++)
                #pragma unroll
                for (int nt = 0; nt < 2; nt++) {
                    mma_tf32(c[mt][nt], aL[mt], bH[nt]);
                    mma_tf32(c[mt][nt], aH[mt], bL[nt]);
                    mma_tf32(c[mt][nt], aH[mt], bH[nt]);
                }
        }
        __syncthreads();
    }

    // epilogue
    #pragma unroll
    for (int mt = 0; mt < 2; mt++) {
        #pragma unroll
        for (int nt = 0; nt < 2; nt++) {
            int r0 = m0 + warp_m * 32 + mt * 16 + g;
            int cb = n0 + warp_n * 16 + nt * 8 + tig * 2;
            #pragma unroll
            for (int half = 0; half < 2; half++) {
                int r = r0 + half * 8;
                if (r >= S) continue;
                #pragma unroll
                for (int j = 0; j < 2; j++) {
                    int n = cb + j;
                    if (n >= N) continue;
                    float v = c[mt][nt][half * 2 + j];
                    if (bias) v += bias[n];
                    if (res)  v += res[(size_t)r * N + n];
                    if (RELU) v = fmaxf(v, 0.f);
                    C[(size_t)r * N + n] = v;
                }
            }
        }
    }
}

static void gemm(const float* A, const float* W, const float* bias,
                 const float* res, float* C, int S, int N, int K, bool relu) {
    dim3 grid((N + 63) / 64, (S + 63) / 64);
    if (relu) gemm_tc_kernel<true ><<<grid, 256>>>(A, W, bias, res, C, S, N, K);
    else      gemm_tc_kernel<false><<<grid, 256>>>(A, W, bias, res, C, S, N, K);
}

// ---------------- flash attention v2 (fp32, online softmax) ----------------
// 128 q rows / block, 256 threads: thread = (row = tid>>1, half = tid&1).
__global__ __launch_bounds__(256)
void flash_kernel(const float* __restrict__ q,
                  const float* __restrict__ k,
                  const float* __restrict__ v,
                  float* __restrict__ o) {
    const int S = S_ROWS, D = DIM;
    const int head = blockIdx.y;
    const int s0 = blockIdx.x * 128;
    const int tid = threadIdx.x;
    const int row = tid >> 1;
    const int half = tid & 1;
    const int srow = s0 + row;

    __shared__ float ks[64][36];
    __shared__ float vs[64][36];

    float qreg[32];
    #pragma unroll
    for (int d4 = 0; d4 < 8; d4++) {
        float4 t4 = (srow < S)
            ? *(const float4*)&q[(size_t)srow * D + head * 32 + d4 * 4]
            : make_float4(0.f, 0.f, 0.f, 0.f);
        qreg[d4 * 4 + 0] = t4.x; qreg[d4 * 4 + 1] = t4.y;
        qreg[d4 * 4 + 2] = t4.z; qreg[d4 * 4 + 3] = t4.w;
    }

    float acc[32];
    #pragma unroll
    for (int i = 0; i < 32; i++) acc[i] = 0.f;
    float m = -INFINITY, l = 0.f;
    const float scl = 0.17677669529663688f; // 1/sqrt(32)

    for (int t0 = 0; t0 < S; t0 += 64) {
        #pragma unroll
        for (int i = 0; i < 2; i++) {
            int f4 = i * 256 + tid;     // 0..511
            int r = f4 >> 3;
            int c4 = (f4 & 7) * 4;
            int t = t0 + r;
            float4 kv4 = (t < S)
                ? *(const float4*)&k[(size_t)t * D + head * 32 + c4]
                : make_float4(0.f, 0.f, 0.f, 0.f);
            *(float4*)&ks[r][c4] = kv4;
            float4 vv4 = (t < S)
                ? *(const float4*)&v[(size_t)t * D + head * 32 + c4]
                : make_float4(0.f, 0.f, 0.f, 0.f);
            *(float4*)&vs[r][c4] = vv4;
        }
        __syncthreads();

        float p[32];
        float mloc = -INFINITY;
        #pragma unroll
        for (int j = 0; j < 32; j++) {
            int t = half * 32 + j;
            float sc = 0.f;
            #pragma unroll
            for (int d4 = 0; d4 < 8; d4++) {
                float4 k4 = *(const float4*)&ks[t][d4 * 4];
                sc += qreg[d4 * 4 + 0] * k4.x + qreg[d4 * 4 + 1] * k4.y
                    + qreg[d4 * 4 + 2] * k4.z + qreg[d4 * 4 + 3] * k4.w;
            }
            sc = (t0 + t < S) ? sc * scl : -INFINITY;
            p[j] = sc;
            mloc = fmaxf(mloc, sc);
        }
        mloc = fmaxf(mloc, __shfl_xor_sync(0xffffffffu, mloc, 1));
        float mnew = fmaxf(m, mloc);
        float corr = expf(m - mnew);
        float lloc = 0.f;
        #pragma unroll
        for (int j = 0; j < 32; j++) {
            float e = expf(p[j] - mnew);   // -inf -> 0
            p[j] = e;
            lloc += e;
        }
        lloc += __shfl_xor_sync(0xffffffffu, lloc, 1);
        l = l * corr + lloc;
        m = mnew;

        #pragma unroll
        for (int i = 0; i < 32; i++) acc[i] *= corr;

        #pragma unroll
        for (int j = 0; j < 32; j++) {
            int t = half * 32 + j;
            float pv = p[j];
            #pragma unroll
            for (int d4 = 0; d4 < 8; d4++) {
                float4 v4 = *(const float4*)&vs[t][d4 * 4];
                acc[d4 * 4 + 0] += pv * v4.x;
                acc[d4 * 4 + 1] += pv * v4.y;
                acc[d4 * 4 + 2] += pv * v4.z;
                acc[d4 * 4 + 3] += pv * v4.w;
            }
        }
        __syncthreads();
    }

    {
        float inv = 1.f / l;
        #pragma unroll
        for (int i = 0; i < 16; i++) {
            float mine = half ? acc[16 + i] : acc[i];
            float send = half ? acc[i]      : acc[16 + i];
            float recv = __shfl_xor_sync(0xffffffffu, send, 1);
            if (srow < S)
                o[(size_t)srow * D + head * 32 + half * 16 + i] = (mine + recv) * inv;
        }
    }
}

// ---------------- RQS spline ------------------------------------------------
__device__ __forceinline__ float softplusf(float x) {
    return (x > 20.f) ? x : log1pf(expf(x));
}

__global__ void spline_kernel(const float* __restrict__ pos,
                              const float* __restrict__ params,
                              float* __restrict__ out,
                              float* __restrict__ ld) {
    int s = blockIdx.x * blockDim.x + threadIdx.x;
    if (s >= S_ROWS) return;
    const float* p = params + s * AFF_OUT;
    const float MINB = 1e-4f;
    const float MINS = 1e-4f;

    float x = pos[(s + 1) * 3 + 2];
    bool inside = (x >= 0.f) && (x <= 1.f);
    float xc = fminf(fmaxf(x, 0.f), 1.f);

    float ew[NB], eh[NB];
    float mw = -INFINITY, mh = -INFINITY;
    #pragma unroll
    for (int i = 0; i < NB; i++) { mw = fmaxf(mw, p[i]); mh = fmaxf(mh, p[NB + i]); }
    float sw = 0.f, sh = 0.f;
    #pragma unroll
    for (int i = 0; i < NB; i++) {
        ew[i] = expf(p[i] - mw);        sw += ew[i];
        eh[i] = expf(p[NB + i] - mh);   sh += eh[i];
    }
    float fac = 1.f - NB * MINB;
    float isw = fac / sw, ish = fac / sh;

    float off = logf(expm1f(1.f - MINS));
    float d[NB + 1];
    #pragma unroll
    for (int i = 0; i < NB; i++) d[i] = softplusf(p[2 * NB + i] + off) + MINS;
    d[NB] = d[0];

    float xp[NB + 1], yp[NB + 1];
    xp[0] = 0.f; yp[0] = 0.f;
    #pragma unroll
    for (int i = 0; i < NB; i++) {
        xp[i + 1] = xp[i] + (ew[i] * isw + MINB);
        yp[i + 1] = yp[i] + (eh[i] * ish + MINB);
    }

    int cnt = 0;
    #pragma unroll
    for (int i = 0; i < NB + 1; i++) cnt += (xc >= xp[i]) ? 1 : 0;
    int kb = cnt - 1;
    if (kb < 0) kb = 0;
    if (kb > NB - 1) kb = NB - 1;

    float xk = xp[kb], xk1 = xp[kb + 1];
    float yk = yp[kb], yk1 = yp[kb + 1];
    float dk = d[kb],  dk1 = d[kb + 1];
    float w = xk1 - xk;
    float h = yk1 - yk;
    float sl = h / w;
    float z = (xc - xk) / w;
    float z1 = 1.f - z;
    float den = sl + (dk1 + dk - 2.f * sl) * z * z1;
    float y = yk + h * (sl * z * z + dk * z * z1) / den;
    float logdet = 2.f * logf(sl)
                 + logf(dk1 * z * z + 2.f * sl * z * z1 + dk * z1 * z1)
                 - 2.f * logf(den);

    out[(s + 1) * 3 + 2] = inside ? y : x;
    ld[s] = inside ? logdet : 0.f;
}

// ---------------- output copy + deterministic logdet reduction -------------
__global__ void copy_pos_kernel(const float* __restrict__ pos,
                                float* __restrict__ out, int n) {
    int i = blockIdx.x * blockDim.x + threadIdx.x;
    if (i < n) out[i] = pos[i];
}

__global__ void reduce_kernel(const float* __restrict__ ld,
                              float* __restrict__ out, int out_size) {
    __shared__ float sh[256];
    float s = 0.f;
    for (int i = threadIdx.x; i < S_ROWS; i += 256) s += ld[i];
    sh[threadIdx.x] = s;
    __syncthreads();
    for (int st = 128; st > 0; st >>= 1) {
        if (threadIdx.x < st) sh[threadIdx.x] += sh[threadIdx.x + st];
        __syncthreads();
    }
    if (threadIdx.x == 0 && out_size > POS_ELEMS) out[POS_ELEMS] = sh[0];
}

// ---------------- host orchestration ---------------------------------------
template <typename T>
static float* sym_addr(T& sym) {
    void* p = nullptr;
    cudaGetSymbolAddress(&p, sym);
    return (float*)p;
}

extern "C" void kernel_launch(void* const* d_in, const int* in_sizes, int n_in,
                              void* d_out, int out_size) {
    const float* pos   = (const float*)d_in[0];
    const float* scale = (const float*)d_in[1];
    const float* press = (const float*)d_in[2];
    const float* temp  = (const float*)d_in[3];
    const float* e_w0 = (const float*)d_in[4];
    const float* e_b0 = (const float*)d_in[5];
    const float* e_w1 = (const float*)d_in[6];
    const float* e_b1 = (const float*)d_in[7];
    const float* e_w2 = (const float*)d_in[8];
    const float* e_b2 = (const float*)d_in[9];
    const float* Wq   = (const float*)d_in[10];
    const float* Wk   = (const float*)d_in[11];
    const float* bk   = (const float*)d_in[12];
    const float* Wv   = (const float*)d_in[13];
    const float* Wo   = (const float*)d_in[14];
    const float* bo   = (const float*)d_in[15];
    const float* mw0  = (const float*)d_in[16];
    const float* mb0  = (const float*)d_in[17];
    const float* mw1  = (const float*)d_in[18];
    const float* mb1  = (const float*)d_in[19];
    const float* mw2  = (const float*)d_in[20];
    const float* mb2  = (const float*)d_in[21];
    const float* a_w0 = (const float*)d_in[22];
    const float* a_b0 = (const float*)d_in[23];
    const float* a_w1 = (const float*)d_in[24];
    const float* a_b1 = (const float*)d_in[25];
    const float* a_w2 = (const float*)d_in[26];
    const float* a_b2 = (const float*)d_in[27];

    float* cond   = sym_addr(g_cond);
    float* bufA   = sym_addr(g_a);
    float* bufB   = sym_addr(g_b);
    float* h      = sym_addr(g_h);
    float* t      = sym_addr(g_t);
    float* q      = sym_addr(g_q);
    float* k      = sym_addr(g_k);
    float* v      = sym_addr(g_v);
    float* params = sym_addr(g_params);
    float* ld     = sym_addr(g_ld);
    float* out    = (float*)d_out;

    embed_kernel<<<(S_ROWS + 255) / 256, 256>>>(pos, scale, press, temp, cond);

    // embedding MLP: 35 -> 512 -> 512 -> 256
    gemm(cond, e_w0, e_b0, nullptr, bufA, S_ROWS, HID, EMB_IN, true);
    gemm(bufA, e_w1, e_b1, nullptr, bufB, S_ROWS, HID, HID, true);
    gemm(bufB, e_w2, e_b2, nullptr, h,    S_ROWS, DIM, HID, false);

    for (int i = 0; i < NBLK; i++) {
        const float* Wqi = Wq + (size_t)i * DIM * DIM;
        const float* Wki = Wk + (size_t)i * DIM * DIM;
        const float* bki = bk + (size_t)i * DIM;
        const float* Wvi = Wv + (size_t)i * DIM * DIM;
        const float* Woi = Wo + (size_t)i * DIM * DIM;
        const float* boi = bo + (size_t)i * DIM;
        const float* mw0i = mw0 + (size_t)i * HID * DIM;
        const float* mb0i = mb0 + (size_t)i * HID;
        const float* mw1i = mw1 + (size_t)i * HID * HID;
        const float* mb1i = mb1 + (size_t)i * HID;
        const float* mw2i = mw2 + (size_t)i * DIM * HID;
        const float* mb2i = mb2 + (size_t)i * DIM;

        gemm(h, Wqi, nullptr, nullptr, q, S_ROWS, DIM, DIM, false);
        gemm(h, Wki, bki,     nullptr, k, S_ROWS, DIM, DIM, false);
        gemm(h, Wvi, nullptr, nullptr, v, S_ROWS, DIM, DIM, false);

        dim3 fgrid((S_ROWS + 127) / 128, NHEAD);
        flash_kernel<<<fgrid, 256>>>(q, k, v, t);

        gemm(t, Woi, boi, h, h, S_ROWS, DIM, DIM, false);

        gemm(h,    mw0i, mb0i, nullptr, bufA, S_ROWS, HID, DIM, true);
        gemm(bufA, mw1i, mb1i, nullptr, bufB, S_ROWS, HID, HID, true);
        gemm(bufB, mw2i, mb2i, h,       h,    S_ROWS, DIM, HID, false);
    }

    // affine head: 256 -> 512 -> 512 -> 49
    gemm(h,    a_w0, a_b0, nullptr, bufA,   S_ROWS, HID,     DIM, true);
    gemm(bufA, a_w1, a_b1, nullptr, bufB,   S_ROWS, HID,     HID, true);
    gemm(bufB, a_w2, a_b2, nullptr, params, S_ROWS, AFF_OUT, HID, false);

    int ncopy = out_size < POS_ELEMS ? out_size : POS_ELEMS;
    copy_pos_kernel<<<(ncopy + 255) / 256, 256>>>(pos, out, ncopy);
    spline_kernel<<<(S_ROWS + 255) / 256, 256>>>(pos, params, out, ld);
    reduce_kernel<<<1, 256>>>(ld, out, out_size);
}

// round 4
// speedup vs baseline: 2.3711x; 1.4782x over previous
#include <cuda_runtime.h>
#include <cstdint>
#include <math.h>

// ---------------- problem constants ----------------
#define S_ROWS 2047          // N_PART - 1
#define DIM    256
#define HID    512
#define NB     16            // N_BINS
#define NFREQ  8
#define NBLK   4
#define NHEAD  8
#define EMB_IN 35            // 2*8*2 + 3
#define AFF_OUT 49           // 3*16 + 1
#define POS_ELEMS (2048*3)

// flash dynamic smem: Ks[64][36] + Vs[64][36] + Ps[64][68], all uint2
#define FLASH_SMEM ((64*36 + 64*36 + 64*68) * 8)

// ---------------- scratch (static device memory; no allocs allowed) -------
__device__ float g_cond[S_ROWS * EMB_IN];
__device__ float g_a[S_ROWS * HID];
__device__ float g_b[S_ROWS * HID];
__device__ float g_h[S_ROWS * DIM];
__device__ float g_t[S_ROWS * DIM];
__device__ float g_q[S_ROWS * DIM];
__device__ float g_k[S_ROWS * DIM];
__device__ float g_v[S_ROWS * DIM];
__device__ float g_params[S_ROWS * AFF_OUT];
__device__ float g_ld[S_ROWS];

// ---------------- helpers ---------------------------------------------------
__device__ __forceinline__ uint32_t f2tf32(float f) {
    uint32_t u;
    asm("cvt.rna.tf32.f32 %0, %1;" : "=r"(u) : "f"(f));
    return u;
}

__device__ __forceinline__ uint2 split_tf32(float f) {
    uint32_t hi = f2tf32(f);
    uint32_t lo = f2tf32(f - __uint_as_float(hi));
    return make_uint2(hi, lo);
}

__device__ __forceinline__ void mma_tf32(float c[4], const uint32_t a[4],
                                         const uint32_t b[2]) {
    asm volatile(
        "mma.sync.aligned.m16n8k8.row.col.f32.tf32.tf32.f32 "
        "{%0,%1,%2,%3}, {%4,%5,%6,%7}, {%8,%9}, {%0,%1,%2,%3};"
        : "+f"(c[0]), "+f"(c[1]), "+f"(c[2]), "+f"(c[3])
        : "r"(a[0]), "r"(a[1]), "r"(a[2]), "r"(a[3]), "r"(b[0]), "r"(b[1]));
}

// 3-term error-compensated tf32 mma
__device__ __forceinline__ void mma3(float c[4], const uint32_t aH[4],
                                     const uint32_t aL[4], const uint32_t bH[2],
                                     const uint32_t bL[2]) {
    mma_tf32(c, aL, bH);
    mma_tf32(c, aH, bL);
    mma_tf32(c, aH, bH);
}

// ---------------- circular features + conditioning vector -----------------
__global__ void embed_kernel(const float* __restrict__ pos,
                             const float* __restrict__ scale,
                             const float* __restrict__ press,
                             const float* __restrict__ temp,
                             float* __restrict__ cond) {
    int s = blockIdx.x * blockDim.x + threadIdx.x;
    if (s >= S_ROWS) return;
    const float TWO_PI = 6.28318530717958647692f;
    float xs[2];
    xs[0] = pos[(s + 1) * 3 + 0];
    xs[1] = pos[(s + 1) * 3 + 1];
    float* c = cond + s * EMB_IN;
    #pragma unroll
    for (int cc = 0; cc < 2; cc++) {
        float x = xs[cc];
        #pragma unroll
        for (int f = 1; f <= NFREQ; f++) {
            float sn, cs;
            sincosf(TWO_PI * (float)f * x, &sn, &cs);
            c[cc * 16 + (f - 1)]     = cs;
            c[cc * 16 + 8 + (f - 1)] = sn;
        }
    }
    c[32] = *scale;
    c[33] = *temp;
    c[34] = *press;
}

// ---------------- 3xTF32 GEMM core: 32x64 tile, 8 warps --------------------
// C[SxN] = A[SxK] @ W[NxK]^T (+bias)(+res)(relu). Warp tile 16x16.
// hi/lo tf32 interleaved as uint2 in smem -> fragment loads are LDS.64.
template <bool RELU>
__device__ __forceinline__
void gemm_core(const float* __restrict__ A, const float* __restrict__ W,
               const float* __restrict__ bias, const float* __restrict__ res,
               float* __restrict__ C, int S, int N, int K) {
    __shared__ uint2 As[32][36];
    __shared__ uint2 Bs[64][36];

    const int tid  = threadIdx.x;
    const int lane = tid & 31;
    const int wid  = tid >> 5;
    const int warp_m = wid >> 2;        // 0..1 (16 rows each)
    const int warp_n = wid & 3;         // 0..3 (16 cols each)
    const int g   = lane >> 2;
    const int tig = lane & 3;

    const int m0 = blockIdx.y * 32;
    const int n0 = blockIdx.x * 64;

    // A: 32x32 floats/stage, 256 thr -> 1 float4 each
    const int aRow = tid >> 3;          // 0..31
    const int aCol = (tid & 7) * 4;
    // B: 64x32/stage -> 2 float4 each
    int bRow[2], bCol[2];
    #pragma unroll
    for (int i = 0; i < 2; i++) {
        int f4 = i * 256 + tid;
        bRow[i] = f4 >> 3;              // 0..63
        bCol[i] = (f4 & 7) * 4;
    }

    float av[4], bv[2][4];
    const int nStages = (K + 31) / 32;

    // prologue
    {
        int m = m0 + aRow;
        #pragma unroll
        for (int j = 0; j < 4; j++)
            av[j] = (m < S && (aCol + j) < K) ? A[(size_t)m * K + aCol + j] : 0.f;
        #pragma unroll
        for (int i = 0; i < 2; i++) {
            int n = n0 + bRow[i];
            #pragma unroll
            for (int j = 0; j < 4; j++)
                bv[i][j] = (n < N && (bCol[i] + j) < K) ? W[(size_t)n * K + bCol[i] + j] : 0.f;
        }
    }

    float c[2][4];
    #pragma unroll
    for (int nt = 0; nt < 2; nt++)
        #pragma unroll
        for (int i = 0; i < 4; i++) c[nt][i] = 0.f;

    for (int s = 0; s < nStages; s++) {
        #pragma unroll
        for (int j = 0; j < 4; j++) As[aRow][aCol + j] = split_tf32(av[j]);
        #pragma unroll
        for (int i = 0; i < 2; i++)
            #pragma unroll
            for (int j = 0; j < 4; j++) Bs[bRow[i]][bCol[i] + j] = split_tf32(bv[i][j]);
        __syncthreads();

        if (s + 1 < nStages) {
            const int k0 = (s + 1) * 32;
            int m = m0 + aRow;
            #pragma unroll
            for (int j = 0; j < 4; j++)
                av[j] = (m < S && (k0 + aCol + j) < K) ? A[(size_t)m * K + k0 + aCol + j] : 0.f;
            #pragma unroll
            for (int i = 0; i < 2; i++) {
                int n = n0 + bRow[i];
                #pragma unroll
                for (int j = 0; j < 4; j++)
                    bv[i][j] = (n < N && (k0 + bCol[i] + j) < K) ? W[(size_t)n * K + k0 + bCol[i] + j] : 0.f;
            }
        }

        #pragma unroll
        for (int k8 = 0; k8 < 4; k8++) {
            const int kk = k8 * 8;
            const int r = warp_m * 16 + g;
            uint2 p0 = As[r    ][kk + tig];
            uint2 p1 = As[r + 8][kk + tig];
            uint2 p2 = As[r    ][kk + tig + 4];
            uint2 p3 = As[r + 8][kk + tig + 4];
            uint32_t aH[4] = {p0.x, p1.x, p2.x, p3.x};
            uint32_t aL[4] = {p0.y, p1.y, p2.y, p3.y};
            #pragma unroll
            for (int nt = 0; nt < 2; nt++) {
                int cidx = warp_n * 16 + nt * 8 + g;
                uint2 q0 = Bs[cidx][kk + tig];
                uint2 q1 = Bs[cidx][kk + tig + 4];
                uint32_t bH[2] = {q0.x, q1.x};
                uint32_t bL[2] = {q0.y, q1.y};
                mma3(c[nt], aH, aL, bH, bL);
            }
        }
        __syncthreads();
    }

    // epilogue
    #pragma unroll
    for (int nt = 0; nt < 2; nt++) {
        int r0 = m0 + warp_m * 16 + g;
        int cb = n0 + warp_n * 16 + nt * 8 + tig * 2;
        #pragma unroll
        for (int half = 0; half < 2; half++) {
            int r = r0 + half * 8;
            if (r >= S) continue;
            #pragma unroll
            for (int j = 0; j < 2; j++) {
                int n = cb + j;
                if (n >= N) continue;
                float v = c[nt][half * 2 + j];
                if (bias) v += bias[n];
                if (res)  v += res[(size_t)r * N + n];
                if (RELU) v = fmaxf(v, 0.f);
                C[(size_t)r * N + n] = v;
            }
        }
    }
}

template <bool RELU>
__global__ __launch_bounds__(256)
void gemm_tc_kernel(const float* __restrict__ A, const float* __restrict__ W,
                    const float* __restrict__ bias, const float* __restrict__ res,
                    float* __restrict__ C, int S, int N, int K) {
    gemm_core<RELU>(A, W, bias, res, C, S, N, K);
}

// fused q/k/v projection: blockIdx.z selects which weight/output
__global__ __launch_bounds__(256)
void gemm_qkv_kernel(const float* __restrict__ h,
                     const float* __restrict__ Wq, const float* __restrict__ Wk,
                     const float* __restrict__ Wv, const float* __restrict__ bk,
                     float* __restrict__ q, float* __restrict__ k,
                     float* __restrict__ v) {
    int z = blockIdx.z;
    const float* W = (z == 0) ? Wq : (z == 1) ? Wk : Wv;
    const float* bias = (z == 1) ? bk : nullptr;
    float* C = (z == 0) ? q : (z == 1) ? k : v;
    gemm_core<false>(h, W, bias, nullptr, C, S_ROWS, DIM, DIM);
}

static void gemm(const float* A, const float* W, const float* bias,
                 const float* res, float* C, int S, int N, int K, bool relu) {
    dim3 grid((N + 63) / 64, (S + 31) / 32);
    if (relu) gemm_tc_kernel<true ><<<grid, 256>>>(A, W, bias, res, C, S, N, K);
    else      gemm_tc_kernel<false><<<grid, 256>>>(A, W, bias, res, C, S, N, K);
}

// ---------------- flash attention, 3xTF32 tensor-core ----------------------
// 64 q rows / block, 4 warps (warp = 16 q rows), one head per blockIdx.y.
// kv tiled by 64. Scores and PV both mma m16n8k8 with 3-term compensation.
__global__ __launch_bounds__(128)
void flash_mma_kernel(const float* __restrict__ q,
                      const float* __restrict__ k,
                      const float* __restrict__ v,
                      float* __restrict__ o) {
    extern __shared__ uint2 smemf[];
    uint2 (*Ks)[36] = (uint2(*)[36])smemf;             // [kv][dim]
    uint2 (*Vs)[36] = (uint2(*)[36])(smemf + 64 * 36); // [kv][dim]
    uint2 (*Ps)[68] = (uint2(*)[68])(smemf + 2 * 64 * 36); // [qrow][kv]

    const int S = S_ROWS, D = DIM;
    const int head = blockIdx.y;
    const int s0 = blockIdx.x * 64;
    const int tid = threadIdx.x;
    const int lane = tid & 31;
    const int wid = tid >> 5;
    const int g = lane >> 2;
    const int tig = lane & 3;
    const float scl = 0.17677669529663688f; // 1/sqrt(32)

    // ---- stage Q (scaled) through Ks, extract per-warp fragments ----
    #pragma unroll
    for (int i = 0; i < 4; i++) {
        int f4 = i * 128 + tid;          // 0..511
        int r = f4 >> 3;                 // 0..63
        int c4 = (f4 & 7) * 4;
        int sr = s0 + r;
        float4 q4 = (sr < S) ? *(const float4*)&q[(size_t)sr * D + head * 32 + c4]
                             : make_float4(0.f, 0.f, 0.f, 0.f);
        Ks[r][c4 + 0] = split_tf32(q4.x * scl);
        Ks[r][c4 + 1] = split_tf32(q4.y * scl);
        Ks[r][c4 + 2] = split_tf32(q4.z * scl);
        Ks[r][c4 + 3] = split_tf32(q4.w * scl);
    }
    __syncthreads();

    uint32_t aQH[4][4], aQL[4][4];
    #pragma unroll
    for (int k8 = 0; k8 < 4; k8++) {
        const int kk = k8 * 8;
        const int r = wid * 16 + g;
        uint2 p0 = Ks[r    ][kk + tig];
        uint2 p1 = Ks[r + 8][kk + tig];
        uint2 p2 = Ks[r    ][kk + tig + 4];
        uint2 p3 = Ks[r + 8][kk + tig + 4];
        aQH[k8][0] = p0.x; aQH[k8][1] = p1.x; aQH[k8][2] = p2.x; aQH[k8][3] = p3.x;
        aQL[k8][0] = p0.y; aQL[k8][1] = p1.y; aQL[k8][2] = p2.y; aQL[k8][3] = p3.y;
    }
    __syncthreads();

    float co[4][4];
    #pragma unroll
    for (int nt = 0; nt < 4; nt++)
        #pragma unroll
        for (int i = 0; i < 4; i++) co[nt][i] = 0.f;
    float m_a = -INFINITY, m_b = -INFINITY, l_a = 0.f, l_b = 0.f;

    for (int t0 = 0; t0 < S; t0 += 64) {
        // ---- load K, V tile (hi/lo split) ----
        #pragma unroll
        for (int i = 0; i < 4; i++) {
            int f4 = i * 128 + tid;
            int r = f4 >> 3;
            int c4 = (f4 & 7) * 4;
            int t = t0 + r;
            float4 k4 = (t < S) ? *(const float4*)&k[(size_t)t * D + head * 32 + c4]
                                : make_float4(0.f, 0.f, 0.f, 0.f);
            Ks[r][c4 + 0] = split_tf32(k4.x);
            Ks[r][c4 + 1] = split_tf32(k4.y);
            Ks[r][c4 + 2] = split_tf32(k4.z);
            Ks[r][c4 + 3] = split_tf32(k4.w);
            float4 v4 = (t < S) ? *(const float4*)&v[(size_t)t * D + head * 32 + c4]
                                : make_float4(0.f, 0.f, 0.f, 0.f);
            Vs[r][c4 + 0] = split_tf32(v4.x);
            Vs[r][c4 + 1] = split_tf32(v4.y);
            Vs[r][c4 + 2] = split_tf32(v4.z);
            Vs[r][c4 + 3] = split_tf32(v4.w);
        }
        __syncthreads();

        // ---- scores: Q(16x32) @ K^T(32x64) -> cs[8 n-tiles][4] ----
        float cs[8][4];
        #pragma unroll
        for (int nt = 0; nt < 8; nt++)
            #pragma unroll
            for (int i = 0; i < 4; i++) cs[nt][i] = 0.f;

        #pragma unroll
        for (int k8 = 0; k8 < 4; k8++) {
            const int kk = k8 * 8;
            #pragma unroll
            for (int nt = 0; nt < 8; nt++) {
                int cidx = nt * 8 + g;
                uint2 q0 = Ks[cidx][kk + tig];
                uint2 q1 = Ks[cidx][kk + tig + 4];
                uint32_t bH[2] = {q0.x, q1.x};
                uint32_t bL[2] = {q0.y, q1.y};
                mma3(cs[nt], aQH[k8], aQL[k8], bH, bL);
            }
        }

        // ---- mask invalid kv cols, row max ----
        float mx_a = m_a, mx_b = m_b;
        #pragma unroll
        for (int nt = 0; nt < 8; nt++) {
            int col0 = t0 + nt * 8 + 2 * tig;
            if (col0 >= S)     { cs[nt][0] = -INFINITY; cs[nt][2] = -INFINITY; }
            if (col0 + 1 >= S) { cs[nt][1] = -INFINITY; cs[nt][3] = -INFINITY; }
            mx_a = fmaxf(mx_a, fmaxf(cs[nt][0], cs[nt][1]));
            mx_b = fmaxf(mx_b, fmaxf(cs[nt][2], cs[nt][3]));
        }
        mx_a = fmaxf(mx_a, __shfl_xor_sync(0xffffffffu, mx_a, 1));
        mx_a = fmaxf(mx_a, __shfl_xor_sync(0xffffffffu, mx_a, 2));
        mx_b = fmaxf(mx_b, __shfl_xor_sync(0xffffffffu, mx_b, 1));
        mx_b = fmaxf(mx_b, __shfl_xor_sync(0xffffffffu, mx_b, 2));
        float corr_a = __expf(m_a - mx_a);
        float corr_b = __expf(m_b - mx_b);
        m_a = mx_a; m_b = mx_b;

        // ---- P = exp(s - m), write hi/lo to Ps, accumulate l ----
        float la = 0.f, lb = 0.f;
        const int rowa = wid * 16 + g;
        #pragma unroll
        for (int nt = 0; nt < 8; nt++) {
            float p0 = __expf(cs[nt][0] - m_a);
            float p1 = __expf(cs[nt][1] - m_a);
            float p2 = __expf(cs[nt][2] - m_b);
            float p3 = __expf(cs[nt][3] - m_b);
            la += p0 + p1;
            lb += p2 + p3;
            int colu = nt * 8 + 2 * tig;
            uint2 h0 = split_tf32(p0), h1 = split_tf32(p1);
            uint2 h2 = split_tf32(p2), h3 = split_tf32(p3);
            *(uint4*)&Ps[rowa    ][colu] = make_uint4(h0.x, h0.y, h1.x, h1.y);
            *(uint4*)&Ps[rowa + 8][colu] = make_uint4(h2.x, h2.y, h3.x, h3.y);
        }
        la += __shfl_xor_sync(0xffffffffu, la, 1);
        la += __shfl_xor_sync(0xffffffffu, la, 2);
        lb += __shfl_xor_sync(0xffffffffu, lb, 1);
        lb += __shfl_xor_sync(0xffffffffu, lb, 2);
        l_a = l_a * corr_a + la;
        l_b = l_b * corr_b + lb;

        #pragma unroll
        for (int nt = 0; nt < 4; nt++) {
            co[nt][0] *= corr_a; co[nt][1] *= corr_a;
            co[nt][2] *= corr_b; co[nt][3] *= corr_b;
        }
        __syncwarp();

        // ---- PV: P(16x64) @ V(64x32) -> co[4 n-tiles][4] ----
        #pragma unroll
        for (int k8v = 0; k8v < 8; k8v++) {
            const int kkv = k8v * 8;
            const int r = wid * 16 + g;
            uint2 p0 = Ps[r    ][kkv + tig];
            uint2 p1 = Ps[r + 8][kkv + tig];
            uint2 p2 = Ps[r    ][kkv + tig + 4];
            uint2 p3 = Ps[r + 8][kkv + tig + 4];
            uint32_t aH[4] = {p0.x, p1.x, p2.x, p3.x};
            uint32_t aL[4] = {p0.y, p1.y, p2.y, p3.y};
            #pragma unroll
            for (int nt = 0; nt < 4; nt++) {
                uint2 q0 = Vs[kkv + tig    ][nt * 8 + g];
                uint2 q1 = Vs[kkv + tig + 4][nt * 8 + g];
                uint32_t bH[2] = {q0.x, q1.x};
                uint32_t bL[2] = {q0.y, q1.y};
                mma3(co[nt], aH, aL, bH, bL);
            }
        }
        __syncthreads();
    }

    // ---- normalize + write ----
    float inv_a = 1.f / l_a;
    float inv_b = 1.f / l_b;
    int srow_a = s0 + wid * 16 + g;
    int srow_b = srow_a + 8;
    #pragma unroll
    for (int nt = 0; nt < 4; nt++) {
        int col = head * 32 + nt * 8 + 2 * tig;
        if (srow_a < S) {
            float2 w2 = make_float2(co[nt][0] * inv_a, co[nt][1] * inv_a);
            *(float2*)&o[(size_t)srow_a * D + col] = w2;
        }
        if (srow_b < S) {
            float2 w2 = make_float2(co[nt][2] * inv_b, co[nt][3] * inv_b);
            *(float2*)&o[(size_t)srow_b * D + col] = w2;
        }
    }
}

// ---------------- RQS spline ------------------------------------------------
__device__ __forceinline__ float softplusf(float x) {
    return (x > 20.f) ? x : log1pf(expf(x));
}

__global__ void spline_kernel(const float* __restrict__ pos,
                              const float* __restrict__ params,
                              float* __restrict__ out,
                              float* __restrict__ ld) {
    int s = blockIdx.x * blockDim.x + threadIdx.x;
    if (s >= S_ROWS) return;
    const float* p = params + s * AFF_OUT;
    const float MINB = 1e-4f;
    const float MINS = 1e-4f;

    float x = pos[(s + 1) * 3 + 2];
    bool inside = (x >= 0.f) && (x <= 1.f);
    float xc = fminf(fmaxf(x, 0.f), 1.f);

    float ew[NB], eh[NB];
    float mw = -INFINITY, mh = -INFINITY;
    #pragma unroll
    for (int i = 0; i < NB; i++) { mw = fmaxf(mw, p[i]); mh = fmaxf(mh, p[NB + i]); }
    float sw = 0.f, sh = 0.f;
    #pragma unroll
    for (int i = 0; i < NB; i++) {
        ew[i] = expf(p[i] - mw);        sw += ew[i];
        eh[i] = expf(p[NB + i] - mh);   sh += eh[i];
    }
    float fac = 1.f - NB * MINB;
    float isw = fac / sw, ish = fac / sh;

    float off = logf(expm1f(1.f - MINS));
    float d[NB + 1];
    #pragma unroll
    for (int i = 0; i < NB; i++) d[i] = softplusf(p[2 * NB + i] + off) + MINS;
    d[NB] = d[0];

    float xp[NB + 1], yp[NB + 1];
    xp[0] = 0.f; yp[0] = 0.f;
    #pragma unroll
    for (int i = 0; i < NB; i++) {
        xp[i + 1] = xp[i] + (ew[i] * isw + MINB);
        yp[i + 1] = yp[i] + (eh[i] * ish + MINB);
    }

    int cnt = 0;
    #pragma unroll
    for (int i = 0; i < NB + 1; i++) cnt += (xc >= xp[i]) ? 1 : 0;
    int kb = cnt - 1;
    if (kb < 0) kb = 0;
    if (kb > NB - 1) kb = NB - 1;

    float xk = xp[kb], xk1 = xp[kb + 1];
    float yk = yp[kb], yk1 = yp[kb + 1];
    float dk = d[kb],  dk1 = d[kb + 1];
    float w = xk1 - xk;
    float h = yk1 - yk;
    float sl = h / w;
    float z = (xc - xk) / w;
    float z1 = 1.f - z;
    float den = sl + (dk1 + dk - 2.f * sl) * z * z1;
    float y = yk + h * (sl * z * z + dk * z * z1) / den;
    float logdet = 2.f * logf(sl)
                 + logf(dk1 * z * z + 2.f * sl * z * z1 + dk * z1 * z1)
                 - 2.f * logf(den);

    out[(s + 1) * 3 + 2] = inside ? y : x;
    ld[s] = inside ? logdet : 0.f;
}

// ---------------- output copy + deterministic logdet reduction -------------
__global__ void copy_pos_kernel(const float* __restrict__ pos,
                                float* __restrict__ out, int n) {
    int i = blockIdx.x * blockDim.x + threadIdx.x;
    if (i < n) out[i] = pos[i];
}

__global__ void reduce_kernel(const float* __restrict__ ld,
                              float* __restrict__ out, int out_size) {
    __shared__ float sh[256];
    float s = 0.f;
    for (int i = threadIdx.x; i < S_ROWS; i += 256) s += ld[i];
    sh[threadIdx.x] = s;
    __syncthreads();
    for (int st = 128; st > 0; st >>= 1) {
        if (threadIdx.x < st) sh[threadIdx.x] += sh[threadIdx.x + st];
        __syncthreads();
    }
    if (threadIdx.x == 0 && out_size > POS_ELEMS) out[POS_ELEMS] = sh[0];
}

// ---------------- host orchestration ---------------------------------------
template <typename T>
static float* sym_addr(T& sym) {
    void* p = nullptr;
    cudaGetSymbolAddress(&p, sym);
    return (float*)p;
}

extern "C" void kernel_launch(void* const* d_in, const int* in_sizes, int n_in,
                              void* d_out, int out_size) {
    const float* pos   = (const float*)d_in[0];
    const float* scale = (const float*)d_in[1];
    const float* press = (const float*)d_in[2];
    const float* temp  = (const float*)d_in[3];
    const float* e_w0 = (const float*)d_in[4];
    const float* e_b0 = (const float*)d_in[5];
    const float* e_w1 = (const float*)d_in[6];
    const float* e_b1 = (const float*)d_in[7];
    const float* e_w2 = (const float*)d_in[8];
    const float* e_b2 = (const float*)d_in[9];
    const float* Wq   = (const float*)d_in[10];
    const float* Wk   = (const float*)d_in[11];
    const float* bk   = (const float*)d_in[12];
    const float* Wv   = (const float*)d_in[13];
    const float* Wo   = (const float*)d_in[14];
    const float* bo   = (const float*)d_in[15];
    const float* mw0  = (const float*)d_in[16];
    const float* mb0  = (const float*)d_in[17];
    const float* mw1  = (const float*)d_in[18];
    const float* mb1  = (const float*)d_in[19];
    const float* mw2  = (const float*)d_in[20];
    const float* mb2  = (const float*)d_in[21];
    const float* a_w0 = (const float*)d_in[22];
    const float* a_b0 = (const float*)d_in[23];
    const float* a_w1 = (const float*)d_in[24];
    const float* a_b1 = (const float*)d_in[25];
    const float* a_w2 = (const float*)d_in[26];
    const float* a_b2 = (const float*)d_in[27];

    float* cond   = sym_addr(g_cond);
    float* bufA   = sym_addr(g_a);
    float* bufB   = sym_addr(g_b);
    float* h      = sym_addr(g_h);
    float* t      = sym_addr(g_t);
    float* q      = sym_addr(g_q);
    float* k      = sym_addr(g_k);
    float* v      = sym_addr(g_v);
    float* params = sym_addr(g_params);
    float* ld     = sym_addr(g_ld);
    float* out    = (float*)d_out;

    static bool attr_done = false;
    if (!attr_done) {
        cudaFuncSetAttribute(flash_mma_kernel,
                             cudaFuncAttributeMaxDynamicSharedMemorySize,
                             FLASH_SMEM);
        attr_done = true;
    }

    embed_kernel<<<(S_ROWS + 255) / 256, 256>>>(pos, scale, press, temp, cond);

    // embedding MLP: 35 -> 512 -> 512 -> 256
    gemm(cond, e_w0, e_b0, nullptr, bufA, S_ROWS, HID, EMB_IN, true);
    gemm(bufA, e_w1, e_b1, nullptr, bufB, S_ROWS, HID, HID, true);
    gemm(bufB, e_w2, e_b2, nullptr, h,    S_ROWS, DIM, HID, false);

    for (int i = 0; i < NBLK; i++) {
        const float* Wqi = Wq + (size_t)i * DIM * DIM;
        const float* Wki = Wk + (size_t)i * DIM * DIM;
        const float* bki = bk + (size_t)i * DIM;
        const float* Wvi = Wv + (size_t)i * DIM * DIM;
        const float* Woi = Wo + (size_t)i * DIM * DIM;
        const float* boi = bo + (size_t)i * DIM;
        const float* mw0i = mw0 + (size_t)i * HID * DIM;
        const float* mb0i = mb0 + (size_t)i * HID;
        const float* mw1i = mw1 + (size_t)i * HID * HID;
        const float* mb1i = mb1 + (size_t)i * HID;
        const float* mw2i = mw2 + (size_t)i * DIM * HID;
        const float* mb2i = mb2 + (size_t)i * DIM;

        // fused q/k/v projections
        dim3 qkvgrid((DIM + 63) / 64, (S_ROWS + 31) / 32, 3);
        gemm_qkv_kernel<<<qkvgrid, 256>>>(h, Wqi, Wki, Wvi, bki, q, k, v);

        dim3 fgrid((S_ROWS + 63) / 64, NHEAD);
        flash_mma_kernel<<<fgrid, 128, FLASH_SMEM>>>(q, k, v, t);

        gemm(t, Woi, boi, h, h, S_ROWS, DIM, DIM, false);

        gemm(h,    mw0i, mb0i, nullptr, bufA, S_ROWS, HID, DIM, true);
        gemm(bufA, mw1i, mb1i, nullptr, bufB, S_ROWS, HID, HID, true);
        gemm(bufB, mw2i, mb2i, h,       h,    S_ROWS, DIM, HID, false);
    }

    // affine head: 256 -> 512 -> 512 -> 49
    gemm(h,    a_w0, a_b0, nullptr, bufA,   S_ROWS, HID,     DIM, true);
    gemm(bufA, a_w1, a_b1, nullptr, bufB,   S_ROWS, HID,     HID, true);
    gemm(bufB, a_w2, a_b2, nullptr, params, S_ROWS, AFF_OUT, HID, false);

    int ncopy = out_size < POS_ELEMS ? out_size : POS_ELEMS;
    copy_pos_kernel<<<(ncopy + 255) / 256, 256>>>(pos, out, ncopy);
    spline_kernel<<<(S_ROWS + 255) / 256, 256>>>(pos, params, out, ld);
    reduce_kernel<<<1, 256>>>(ld, out, out_size);
}